// round 3
// baseline (speedup 1.0000x reference)
#include <cuda_runtime.h>

#define TT 32
#define NN 20000
#define FF 128
#define HH 128
#define CC 10
#define LN_EPS 1e-5f
#define PITCH 132

typedef unsigned long long u64;

// Scratch: P[t][n][h] = X[t] @ W_ih^T + (b_ih + b_hh)
__device__ float g_P[(size_t)TT * NN * HH];

__device__ __forceinline__ u64 pack2(float lo, float hi) {
    u64 r;
    asm("mov.b64 %0, {%1, %2};" : "=l"(r) : "f"(lo), "f"(hi));
    return r;
}
__device__ __forceinline__ void unpack2(u64 v, float& lo, float& hi) {
    asm("mov.b64 {%0, %1}, %2;" : "=f"(lo), "=f"(hi) : "l"(v));
}
__device__ __forceinline__ void ffma2(u64& d, u64 a, u64 b) {
    asm("fma.rn.f32x2 %0, %1, %2, %3;" : "=l"(d) : "l"(a), "l"(b), "l"(d));
}

// ---------------------------------------------------------------------------
// Kernel A: P = X @ W_ih^T + (b_ih + b_hh)
// M = T*N = 640000 rows, K = F = 128, N' = H = 128.
// 128-row tiles, 256 threads, each thread computes an 8x8 microtile.
// ---------------------------------------------------------------------------
__global__ void __launch_bounds__(256) proj_kernel(
    const float* __restrict__ X, const float* __restrict__ W_ih,
    const float* __restrict__ b_ih, const float* __restrict__ b_hh)
{
    extern __shared__ float sm[];
    float* Xs = sm;                  // [128][PITCH]
    float* Ws = sm + 128 * PITCH;    // [f][j] = W_ih[j][f]

    const int tid = threadIdx.x;
    const long row_base = (long)blockIdx.x * 128;

    // Load W_ih transposed into SMEM
    for (int i = tid * 4; i < HH * FF; i += 256 * 4) {
        float4 w = *(const float4*)(W_ih + i);
        int j = i >> 7, f = i & 127;
        Ws[(f + 0) * PITCH + j] = w.x;
        Ws[(f + 1) * PITCH + j] = w.y;
        Ws[(f + 2) * PITCH + j] = w.z;
        Ws[(f + 3) * PITCH + j] = w.w;
    }
    // Load X tile (128 rows x 128 cols), coalesced
    const float* Xblk = X + row_base * FF;
    for (int i = tid * 4; i < 128 * FF; i += 256 * 4) {
        float4 v = *(const float4*)(Xblk + i);
        int r = i >> 7, c = i & 127;
        *(float4*)(Xs + r * PITCH + c) = v;
    }
    __syncthreads();

    const int ty = tid >> 4, tx = tid & 15;
    const int i0 = ty * 8, j0 = tx * 8;

    // Bias init (b_ih + b_hh), same for every row of the microtile
    u64 bp[4];
    {
        float bb[8];
        #pragma unroll
        for (int j = 0; j < 8; j++) bb[j] = b_ih[j0 + j] + b_hh[j0 + j];
        bp[0] = pack2(bb[0], bb[1]); bp[1] = pack2(bb[2], bb[3]);
        bp[2] = pack2(bb[4], bb[5]); bp[3] = pack2(bb[6], bb[7]);
    }
    u64 acc[8][4];
    #pragma unroll
    for (int i = 0; i < 8; i++) {
        acc[i][0] = bp[0]; acc[i][1] = bp[1];
        acc[i][2] = bp[2]; acc[i][3] = bp[3];
    }

    #pragma unroll 4
    for (int k = 0; k < FF; k++) {
        const float* wr = Ws + k * PITCH + j0;
        ulonglong2 bA = *(const ulonglong2*)(wr);
        ulonglong2 bB = *(const ulonglong2*)(wr + 4);
        const float* ar = Xs + i0 * PITCH + k;
        #pragma unroll
        for (int i = 0; i < 8; i++) {
            float av = ar[i * PITCH];
            u64 a2 = pack2(av, av);
            ffma2(acc[i][0], a2, bA.x);
            ffma2(acc[i][1], a2, bA.y);
            ffma2(acc[i][2], a2, bB.x);
            ffma2(acc[i][3], a2, bB.y);
        }
    }

    float* Prow = g_P + row_base * HH;
    #pragma unroll
    for (int i = 0; i < 8; i++) {
        float4 v0, v1;
        unpack2(acc[i][0], v0.x, v0.y); unpack2(acc[i][1], v0.z, v0.w);
        unpack2(acc[i][2], v1.x, v1.y); unpack2(acc[i][3], v1.z, v1.w);
        *(float4*)(Prow + (long)(i0 + i) * HH + j0) = v0;
        *(float4*)(Prow + (long)(i0 + i) * HH + j0 + 4) = v1;
    }
}

// ---------------------------------------------------------------------------
// Kernel B: recurrence + fused LN + attention (online softmax over t) + dense.
// 125 blocks x 160 rows (exactly 20000). 320 threads.
// GEMM phase: 20 x 16 thread grid, 8x8 microtile.
// Epilogue phase: 2 threads per row (tid>>1 = row, tid&1 = half of 128 cols).
// ---------------------------------------------------------------------------
#define MB 160
#define NTHR 320

__global__ void __launch_bounds__(NTHR) rnn_kernel(
    const float* __restrict__ W_hh,
    const float* __restrict__ ln_g, const float* __restrict__ ln_b,
    const float* __restrict__ attn_W,
    const float* __restrict__ dense_W, const float* __restrict__ dense_b,
    float* __restrict__ out)
{
    extern __shared__ float sm[];
    float* Ws = sm;                         // [k][j] = W_hh[j][k], 128*PITCH
    float* Hs = Ws + 128 * PITCH;           // [row][k], 160*PITCH
    float* Dw = Hs + MB * PITCH;            // [10][128]
    float* Aw = Dw + CC * HH;               // [128]
    float* Gm = Aw + HH;                    // [128]
    float* Bt = Gm + HH;                    // [128]

    const int tid = threadIdx.x;
    const long row_base = (long)blockIdx.x * MB;

    // W_hh transposed into SMEM
    for (int i = tid * 4; i < HH * HH; i += NTHR * 4) {
        float4 w = *(const float4*)(W_hh + i);
        int j = i >> 7, k = i & 127;
        Ws[(k + 0) * PITCH + j] = w.x;
        Ws[(k + 1) * PITCH + j] = w.y;
        Ws[(k + 2) * PITCH + j] = w.z;
        Ws[(k + 3) * PITCH + j] = w.w;
    }
    for (int i = tid; i < CC * HH; i += NTHR) Dw[i] = dense_W[i];
    if (tid < HH) { Aw[tid] = attn_W[tid]; Gm[tid] = ln_g[tid]; Bt[tid] = ln_b[tid]; }

    // h0 = P[0]  (no relu, per reference init branch)
    {
        const float* P0 = g_P + row_base * HH;
        for (int i = tid * 4; i < MB * HH; i += NTHR * 4) {
            float4 v = *(const float4*)(P0 + i);
            int r = i >> 7, c = i & 127;
            *(float4*)(Hs + r * PITCH + c) = v;
        }
    }
    __syncthreads();

    const int ty = tid >> 4, tx = tid & 15;    // 20 x 16
    const int i0 = ty * 8, j0 = tx * 8;

    const int erow = tid >> 1;                 // epilogue row 0..159
    const int half = tid & 1;                  // which 64-col half

    // Online softmax state (replicated identically in both lanes of a pair)
    float m = -1e30f, ssum = 0.f;
    float accc[CC];
    #pragma unroll
    for (int c = 0; c < CC; c++) accc[c] = 0.f;

    for (int t = 0; t < TT; t++) {
        // ---- GEMM: acc = P[t] + h @ W_hh^T ----
        const float* Pt = g_P + ((long)t * NN + row_base) * HH;
        u64 acc[8][4];
        #pragma unroll
        for (int i = 0; i < 8; i++) {
            const float* pr = Pt + (long)(i0 + i) * HH + j0;
            ulonglong2 p0 = *(const ulonglong2*)(pr);
            ulonglong2 p1 = *(const ulonglong2*)(pr + 4);
            acc[i][0] = p0.x; acc[i][1] = p0.y;
            acc[i][2] = p1.x; acc[i][3] = p1.y;
        }
        #pragma unroll 4
        for (int k = 0; k < HH; k++) {
            const float* wr = Ws + k * PITCH + j0;
            ulonglong2 bA = *(const ulonglong2*)(wr);
            ulonglong2 bB = *(const ulonglong2*)(wr + 4);
            const float* hc = Hs + i0 * PITCH + k;
            #pragma unroll
            for (int i = 0; i < 8; i++) {
                float av = hc[i * PITCH];
                u64 a2 = pack2(av, av);
                ffma2(acc[i][0], a2, bA.x);
                ffma2(acc[i][1], a2, bA.y);
                ffma2(acc[i][2], a2, bB.x);
                ffma2(acc[i][3], a2, bB.y);
            }
        }
        __syncthreads();   // all reads of previous h done

        // ---- relu + write new h ----
        #pragma unroll
        for (int i = 0; i < 8; i++) {
            float4 v0, v1;
            unpack2(acc[i][0], v0.x, v0.y); unpack2(acc[i][1], v0.z, v0.w);
            unpack2(acc[i][2], v1.x, v1.y); unpack2(acc[i][3], v1.z, v1.w);
            v0.x = fmaxf(v0.x, 0.f); v0.y = fmaxf(v0.y, 0.f);
            v0.z = fmaxf(v0.z, 0.f); v0.w = fmaxf(v0.w, 0.f);
            v1.x = fmaxf(v1.x, 0.f); v1.y = fmaxf(v1.y, 0.f);
            v1.z = fmaxf(v1.z, 0.f); v1.w = fmaxf(v1.w, 0.f);
            float* hr = Hs + (i0 + i) * PITCH + j0;
            *(float4*)(hr) = v0;
            *(float4*)(hr + 4) = v1;
        }
        __syncthreads();   // new h visible to everyone

        // ---- fused epilogue: LN + attn logit + dense + online softmax ----
        const float* xr = Hs + erow * PITCH + half * 64;
        float4 xx[16];
        #pragma unroll
        for (int q = 0; q < 16; q++) xx[q] = *(const float4*)(xr + q * 4);

        float s1 = 0.f, s2 = 0.f;
        #pragma unroll
        for (int q = 0; q < 16; q++) {
            s1 += xx[q].x + xx[q].y + xx[q].z + xx[q].w;
            s2 += xx[q].x * xx[q].x + xx[q].y * xx[q].y
                + xx[q].z * xx[q].z + xx[q].w * xx[q].w;
        }
        s1 += __shfl_xor_sync(0xffffffffu, s1, 1);
        s2 += __shfl_xor_sync(0xffffffffu, s2, 1);
        float mean = s1 * (1.f / 128.f);
        float var  = s2 * (1.f / 128.f) - mean * mean;
        float rstd = rsqrtf(var + LN_EPS);

        const float* gp = Gm + half * 64;
        const float* bp = Bt + half * 64;
        const float* ap = Aw + half * 64;
        float l = 0.f;
        #pragma unroll
        for (int q = 0; q < 16; q++) {
            float4 g4 = *(const float4*)(gp + q * 4);
            float4 b4 = *(const float4*)(bp + q * 4);
            float4 a4 = *(const float4*)(ap + q * 4);
            xx[q].x = (xx[q].x - mean) * rstd * g4.x + b4.x;
            xx[q].y = (xx[q].y - mean) * rstd * g4.y + b4.y;
            xx[q].z = (xx[q].z - mean) * rstd * g4.z + b4.z;
            xx[q].w = (xx[q].w - mean) * rstd * g4.w + b4.w;
            l += xx[q].x * a4.x + xx[q].y * a4.y + xx[q].z * a4.z + xx[q].w * a4.w;
        }
        l += __shfl_xor_sync(0xffffffffu, l, 1);
        // attn_b cancels in softmax over t — skip it.

        float dc[CC];
        #pragma unroll
        for (int c = 0; c < CC; c++) {
            const float* dp = Dw + c * HH + half * 64;
            float d = 0.f;
            #pragma unroll
            for (int q = 0; q < 16; q++) {
                float4 w4 = *(const float4*)(dp + q * 4);
                d += xx[q].x * w4.x + xx[q].y * w4.y + xx[q].z * w4.z + xx[q].w * w4.w;
            }
            d += __shfl_xor_sync(0xffffffffu, d, 1);
            dc[c] = d;
        }

        float nm = fmaxf(m, l);
        float eo = __expf(m - nm);
        float en = __expf(l - nm);
        ssum = ssum * eo + en;
        #pragma unroll
        for (int c = 0; c < CC; c++) accc[c] = accc[c] * eo + en * dc[c];
        m = nm;
    }

    // out[n][c] = acc[c]/s + dense_b[c]   (sum of attention weights == 1)
    const long n = row_base + erow;
    float inv = 1.f / ssum;
    #pragma unroll
    for (int c = 0; c < 5; c++) {
        int cc = half * 5 + c;
        out[n * CC + cc] = accc[cc] * inv + dense_b[cc];
    }
}

// ---------------------------------------------------------------------------
extern "C" void kernel_launch(void* const* d_in, const int* in_sizes, int n_in,
                              void* d_out, int out_size) {
    (void)in_sizes; (void)n_in; (void)out_size;
    const float* X       = (const float*)d_in[0];
    const float* W_ih    = (const float*)d_in[1];
    const float* W_hh    = (const float*)d_in[2];
    const float* b_ih    = (const float*)d_in[3];
    const float* b_hh    = (const float*)d_in[4];
    const float* ln_g    = (const float*)d_in[5];
    const float* ln_b    = (const float*)d_in[6];
    const float* attn_W  = (const float*)d_in[7];
    // d_in[8] = attn_b: cancels in softmax over time, unused.
    const float* dense_W = (const float*)d_in[9];
    const float* dense_b = (const float*)d_in[10];
    float* out = (float*)d_out;

    const int smemA = 2 * 128 * PITCH * sizeof(float);                       // 135168
    const int smemB = (128 * PITCH + MB * PITCH + CC * HH + 3 * HH) * sizeof(float); // 158720

    cudaFuncSetAttribute(proj_kernel, cudaFuncAttributeMaxDynamicSharedMemorySize, smemA);
    cudaFuncSetAttribute(rnn_kernel,  cudaFuncAttributeMaxDynamicSharedMemorySize, smemB);

    proj_kernel<<<(TT * NN) / 128, 256, smemA>>>(X, W_ih, b_ih, b_hh);
    rnn_kernel<<<NN / MB, NTHR, smemB>>>(W_hh, ln_g, ln_b, attn_W,
                                         dense_W, dense_b, out);
}

// round 4
// speedup vs baseline: 1.0013x; 1.0013x over previous
#include <cuda_runtime.h>

#define TT 32
#define NN 20000
#define FF 128
#define HH 128
#define CC 10
#define LN_EPS 1e-5f
#define PITCH 132

typedef unsigned long long u64;

// Scratch: P[t][n][h] = X[t] @ W_ih^T + (b_ih + b_hh)
__device__ float g_P[(size_t)TT * NN * HH];

__device__ __forceinline__ u64 pack2(float lo, float hi) {
    u64 r;
    asm("mov.b64 %0, {%1, %2};" : "=l"(r) : "f"(lo), "f"(hi));
    return r;
}
__device__ __forceinline__ void unpack2(u64 v, float& lo, float& hi) {
    asm("mov.b64 {%0, %1}, %2;" : "=f"(lo), "=f"(hi) : "l"(v));
}
__device__ __forceinline__ void ffma2(u64& d, u64 a, u64 b) {
    asm("fma.rn.f32x2 %0, %1, %2, %3;" : "=l"(d) : "l"(a), "l"(b), "l"(d));
}

// ---------------------------------------------------------------------------
// Kernel A: P = X @ W_ih^T + (b_ih + b_hh)
// M = T*N = 640000 rows, K = F = 128, N' = H = 128.
// 128-row tiles, 256 threads, each thread computes an 8x8 microtile.
// ---------------------------------------------------------------------------
__global__ void __launch_bounds__(256) proj_kernel(
    const float* __restrict__ X, const float* __restrict__ W_ih,
    const float* __restrict__ b_ih, const float* __restrict__ b_hh)
{
    extern __shared__ float sm[];
    float* Xs = sm;                  // [128][PITCH]
    float* Ws = sm + 128 * PITCH;    // [f][j] = W_ih[j][f]

    const int tid = threadIdx.x;
    const long row_base = (long)blockIdx.x * 128;

    // Load W_ih transposed into SMEM
    for (int i = tid * 4; i < HH * FF; i += 256 * 4) {
        float4 w = *(const float4*)(W_ih + i);
        int j = i >> 7, f = i & 127;
        Ws[(f + 0) * PITCH + j] = w.x;
        Ws[(f + 1) * PITCH + j] = w.y;
        Ws[(f + 2) * PITCH + j] = w.z;
        Ws[(f + 3) * PITCH + j] = w.w;
    }
    // Load X tile (128 rows x 128 cols), coalesced
    const float* Xblk = X + row_base * FF;
    for (int i = tid * 4; i < 128 * FF; i += 256 * 4) {
        float4 v = *(const float4*)(Xblk + i);
        int r = i >> 7, c = i & 127;
        *(float4*)(Xs + r * PITCH + c) = v;
    }
    __syncthreads();

    const int ty = tid >> 4, tx = tid & 15;
    const int i0 = ty * 8, j0 = tx * 8;

    // Bias init (b_ih + b_hh), same for every row of the microtile
    u64 bp[4];
    {
        float bb[8];
        #pragma unroll
        for (int j = 0; j < 8; j++) bb[j] = b_ih[j0 + j] + b_hh[j0 + j];
        bp[0] = pack2(bb[0], bb[1]); bp[1] = pack2(bb[2], bb[3]);
        bp[2] = pack2(bb[4], bb[5]); bp[3] = pack2(bb[6], bb[7]);
    }
    u64 acc[8][4];
    #pragma unroll
    for (int i = 0; i < 8; i++) {
        acc[i][0] = bp[0]; acc[i][1] = bp[1];
        acc[i][2] = bp[2]; acc[i][3] = bp[3];
    }

    #pragma unroll 4
    for (int k = 0; k < FF; k++) {
        const float* wr = Ws + k * PITCH + j0;
        ulonglong2 bA = *(const ulonglong2*)(wr);
        ulonglong2 bB = *(const ulonglong2*)(wr + 4);
        const float* ar = Xs + i0 * PITCH + k;
        #pragma unroll
        for (int i = 0; i < 8; i++) {
            float av = ar[i * PITCH];
            u64 a2 = pack2(av, av);
            ffma2(acc[i][0], a2, bA.x);
            ffma2(acc[i][1], a2, bA.y);
            ffma2(acc[i][2], a2, bB.x);
            ffma2(acc[i][3], a2, bB.y);
        }
    }

    float* Prow = g_P + row_base * HH;
    #pragma unroll
    for (int i = 0; i < 8; i++) {
        float4 v0, v1;
        unpack2(acc[i][0], v0.x, v0.y); unpack2(acc[i][1], v0.z, v0.w);
        unpack2(acc[i][2], v1.x, v1.y); unpack2(acc[i][3], v1.z, v1.w);
        *(float4*)(Prow + (long)(i0 + i) * HH + j0) = v0;
        *(float4*)(Prow + (long)(i0 + i) * HH + j0 + 4) = v1;
    }
}

// ---------------------------------------------------------------------------
// Kernel B: recurrence + fused LN + attention (online softmax over t) + dense.
// 125 blocks x 160 rows (exactly 20000). 320 threads.
// GEMM phase: 20 x 16 thread grid, 8x8 microtile.
// Epilogue phase: 2 threads per row (tid>>1 = row, tid&1 = half of 128 cols).
// ---------------------------------------------------------------------------
#define MB 160
#define NTHR 320

__global__ void __launch_bounds__(NTHR) rnn_kernel(
    const float* __restrict__ W_hh,
    const float* __restrict__ ln_g, const float* __restrict__ ln_b,
    const float* __restrict__ attn_W,
    const float* __restrict__ dense_W, const float* __restrict__ dense_b,
    float* __restrict__ out)
{
    extern __shared__ float sm[];
    float* Ws = sm;                         // [k][j] = W_hh[j][k], 128*PITCH
    float* Hs = Ws + 128 * PITCH;           // [row][k], 160*PITCH
    float* Dw = Hs + MB * PITCH;            // [10][128]
    float* Aw = Dw + CC * HH;               // [128]
    float* Gm = Aw + HH;                    // [128]
    float* Bt = Gm + HH;                    // [128]

    const int tid = threadIdx.x;
    const long row_base = (long)blockIdx.x * MB;

    // W_hh transposed into SMEM
    for (int i = tid * 4; i < HH * HH; i += NTHR * 4) {
        float4 w = *(const float4*)(W_hh + i);
        int j = i >> 7, k = i & 127;
        Ws[(k + 0) * PITCH + j] = w.x;
        Ws[(k + 1) * PITCH + j] = w.y;
        Ws[(k + 2) * PITCH + j] = w.z;
        Ws[(k + 3) * PITCH + j] = w.w;
    }
    for (int i = tid; i < CC * HH; i += NTHR) Dw[i] = dense_W[i];
    if (tid < HH) { Aw[tid] = attn_W[tid]; Gm[tid] = ln_g[tid]; Bt[tid] = ln_b[tid]; }

    // h0 = P[0]  (no relu, per reference init branch)
    {
        const float* P0 = g_P + row_base * HH;
        for (int i = tid * 4; i < MB * HH; i += NTHR * 4) {
            float4 v = *(const float4*)(P0 + i);
            int r = i >> 7, c = i & 127;
            *(float4*)(Hs + r * PITCH + c) = v;
        }
    }
    __syncthreads();

    const int ty = tid >> 4, tx = tid & 15;    // 20 x 16
    const int i0 = ty * 8, j0 = tx * 8;

    const int erow = tid >> 1;                 // epilogue row 0..159
    const int half = tid & 1;                  // which 64-col half

    // Online softmax state (replicated identically in both lanes of a pair)
    float m = -1e30f, ssum = 0.f;
    float accc[CC];
    #pragma unroll
    for (int c = 0; c < CC; c++) accc[c] = 0.f;

    for (int t = 0; t < TT; t++) {
        // ---- GEMM: acc = P[t] + h @ W_hh^T ----
        const float* Pt = g_P + ((long)t * NN + row_base) * HH;
        u64 acc[8][4];
        #pragma unroll
        for (int i = 0; i < 8; i++) {
            const float* pr = Pt + (long)(i0 + i) * HH + j0;
            ulonglong2 p0 = *(const ulonglong2*)(pr);
            ulonglong2 p1 = *(const ulonglong2*)(pr + 4);
            acc[i][0] = p0.x; acc[i][1] = p0.y;
            acc[i][2] = p1.x; acc[i][3] = p1.y;
        }
        #pragma unroll 4
        for (int k = 0; k < HH; k++) {
            const float* wr = Ws + k * PITCH + j0;
            ulonglong2 bA = *(const ulonglong2*)(wr);
            ulonglong2 bB = *(const ulonglong2*)(wr + 4);
            const float* hc = Hs + i0 * PITCH + k;
            #pragma unroll
            for (int i = 0; i < 8; i++) {
                float av = hc[i * PITCH];
                u64 a2 = pack2(av, av);
                ffma2(acc[i][0], a2, bA.x);
                ffma2(acc[i][1], a2, bA.y);
                ffma2(acc[i][2], a2, bB.x);
                ffma2(acc[i][3], a2, bB.y);
            }
        }
        __syncthreads();   // all reads of previous h done

        // ---- relu + write new h ----
        #pragma unroll
        for (int i = 0; i < 8; i++) {
            float4 v0, v1;
            unpack2(acc[i][0], v0.x, v0.y); unpack2(acc[i][1], v0.z, v0.w);
            unpack2(acc[i][2], v1.x, v1.y); unpack2(acc[i][3], v1.z, v1.w);
            v0.x = fmaxf(v0.x, 0.f); v0.y = fmaxf(v0.y, 0.f);
            v0.z = fmaxf(v0.z, 0.f); v0.w = fmaxf(v0.w, 0.f);
            v1.x = fmaxf(v1.x, 0.f); v1.y = fmaxf(v1.y, 0.f);
            v1.z = fmaxf(v1.z, 0.f); v1.w = fmaxf(v1.w, 0.f);
            float* hr = Hs + (i0 + i) * PITCH + j0;
            *(float4*)(hr) = v0;
            *(float4*)(hr + 4) = v1;
        }
        __syncthreads();   // new h visible to everyone

        // ---- fused epilogue: LN + attn logit + dense + online softmax ----
        const float* xr = Hs + erow * PITCH + half * 64;
        float4 xx[16];
        #pragma unroll
        for (int q = 0; q < 16; q++) xx[q] = *(const float4*)(xr + q * 4);

        float s1 = 0.f, s2 = 0.f;
        #pragma unroll
        for (int q = 0; q < 16; q++) {
            s1 += xx[q].x + xx[q].y + xx[q].z + xx[q].w;
            s2 += xx[q].x * xx[q].x + xx[q].y * xx[q].y
                + xx[q].z * xx[q].z + xx[q].w * xx[q].w;
        }
        s1 += __shfl_xor_sync(0xffffffffu, s1, 1);
        s2 += __shfl_xor_sync(0xffffffffu, s2, 1);
        float mean = s1 * (1.f / 128.f);
        float var  = s2 * (1.f / 128.f) - mean * mean;
        float rstd = rsqrtf(var + LN_EPS);

        const float* gp = Gm + half * 64;
        const float* bp = Bt + half * 64;
        const float* ap = Aw + half * 64;
        float l = 0.f;
        #pragma unroll
        for (int q = 0; q < 16; q++) {
            float4 g4 = *(const float4*)(gp + q * 4);
            float4 b4 = *(const float4*)(bp + q * 4);
            float4 a4 = *(const float4*)(ap + q * 4);
            xx[q].x = (xx[q].x - mean) * rstd * g4.x + b4.x;
            xx[q].y = (xx[q].y - mean) * rstd * g4.y + b4.y;
            xx[q].z = (xx[q].z - mean) * rstd * g4.z + b4.z;
            xx[q].w = (xx[q].w - mean) * rstd * g4.w + b4.w;
            l += xx[q].x * a4.x + xx[q].y * a4.y + xx[q].z * a4.z + xx[q].w * a4.w;
        }
        l += __shfl_xor_sync(0xffffffffu, l, 1);
        // attn_b cancels in softmax over t — skip it.

        float dc[CC];
        #pragma unroll
        for (int c = 0; c < CC; c++) {
            const float* dp = Dw + c * HH + half * 64;
            float d = 0.f;
            #pragma unroll
            for (int q = 0; q < 16; q++) {
                float4 w4 = *(const float4*)(dp + q * 4);
                d += xx[q].x * w4.x + xx[q].y * w4.y + xx[q].z * w4.z + xx[q].w * w4.w;
            }
            d += __shfl_xor_sync(0xffffffffu, d, 1);
            dc[c] = d;
        }

        float nm = fmaxf(m, l);
        float eo = __expf(m - nm);
        float en = __expf(l - nm);
        ssum = ssum * eo + en;
        #pragma unroll
        for (int c = 0; c < CC; c++) accc[c] = accc[c] * eo + en * dc[c];
        m = nm;
    }

    // out[n][c] = acc[c]/s + dense_b[c]   (sum of attention weights == 1)
    const long n = row_base + erow;
    float inv = 1.f / ssum;
    #pragma unroll
    for (int c = 0; c < 5; c++) {
        int cc = half * 5 + c;
        out[n * CC + cc] = accc[cc] * inv + dense_b[cc];
    }
}

// ---------------------------------------------------------------------------
extern "C" void kernel_launch(void* const* d_in, const int* in_sizes, int n_in,
                              void* d_out, int out_size) {
    (void)in_sizes; (void)n_in; (void)out_size;
    const float* X       = (const float*)d_in[0];
    const float* W_ih    = (const float*)d_in[1];
    const float* W_hh    = (const float*)d_in[2];
    const float* b_ih    = (const float*)d_in[3];
    const float* b_hh    = (const float*)d_in[4];
    const float* ln_g    = (const float*)d_in[5];
    const float* ln_b    = (const float*)d_in[6];
    const float* attn_W  = (const float*)d_in[7];
    // d_in[8] = attn_b: cancels in softmax over time, unused.
    const float* dense_W = (const float*)d_in[9];
    const float* dense_b = (const float*)d_in[10];
    float* out = (float*)d_out;

    const int smemA = 2 * 128 * PITCH * sizeof(float);                       // 135168
    const int smemB = (128 * PITCH + MB * PITCH + CC * HH + 3 * HH) * sizeof(float); // 158720

    cudaFuncSetAttribute(proj_kernel, cudaFuncAttributeMaxDynamicSharedMemorySize, smemA);
    cudaFuncSetAttribute(rnn_kernel,  cudaFuncAttributeMaxDynamicSharedMemorySize, smemB);

    proj_kernel<<<(TT * NN) / 128, 256, smemA>>>(X, W_ih, b_ih, b_hh);
    rnn_kernel<<<NN / MB, NTHR, smemB>>>(W_hh, ln_g, ln_b, attn_W,
                                         dense_W, dense_b, out);
}

// round 6
// speedup vs baseline: 3.6545x; 3.6496x over previous
#include <cuda_runtime.h>

typedef unsigned int u32;

#define TT 32
#define NN 20000
#define CC 10
#define NWARP 9
#define NTHR 288
#define MB 144
#define NCTA 139
#define LN_EPS 1e-5f

// SMEM byte offsets
#define S_WIH_HI 0u
#define S_WIH_LO 32768u
#define S_WHH_HI 65536u
#define S_WHH_LO 98304u
#define S_E_HI   131072u
#define S_E_LO   135168u
#define S_BIAS   139264u
#define S_GV     139776u
#define S_BV     139840u
#define S_DB     139904u
#define S_TOTAL  140032u

// split fp32 pair into packed bf16 hi + packed bf16 residual (lo in low half)
__device__ __forceinline__ void split2(float x0, float x1, u32& hi, u32& lo) {
    u32 h;
    asm("cvt.rn.bf16x2.f32 %0, %1, %2;" : "=r"(h) : "f"(x1), "f"(x0));
    float h0 = __uint_as_float(h << 16);
    float h1 = __uint_as_float(h & 0xffff0000u);
    asm("cvt.rn.bf16x2.f32 %0, %1, %2;" : "=r"(lo) : "f"(x1 - h1), "f"(x0 - h0));
    hi = h;
}

__device__ __forceinline__ void mma16816(float* d, const u32* a, u32 b0, u32 b1) {
    asm volatile(
        "mma.sync.aligned.m16n8k16.row.col.f32.bf16.bf16.f32 "
        "{%0,%1,%2,%3},{%4,%5,%6,%7},{%8,%9},{%0,%1,%2,%3};\n"
        : "+f"(d[0]), "+f"(d[1]), "+f"(d[2]), "+f"(d[3])
        : "r"(a[0]), "r"(a[1]), "r"(a[2]), "r"(a[3]), "r"(b0), "r"(b1));
}

__device__ __forceinline__ void ldsm4(u32& r0, u32& r1, u32& r2, u32& r3, u32 addr) {
    asm volatile("ldmatrix.sync.aligned.m8n8.x4.shared.b16 {%0,%1,%2,%3},[%4];\n"
        : "=r"(r0), "=r"(r1), "=r"(r2), "=r"(r3) : "r"(addr));
}

// one K-chunk (16) of a 16x128 GEMM against a 128x128 weight tile (hi/lo)
__device__ __forceinline__ void gemm_chunk(
    float (*acc)[4], const u32* ahi, const u32* alo,
    u32 base_hi, u32 base_lo, u32 rowpart, int khalf, int r, int kc)
{
    u32 sw = (u32)(((2 * kc + khalf) ^ r) << 4);
    u32 ah = base_hi + rowpart + sw;
    u32 al = base_lo + rowpart + sw;
    #pragma unroll
    for (int p = 0; p < 8; p++) {
        u32 bh0, bh1, bh2, bh3, bl0, bl1, bl2, bl3;
        ldsm4(bh0, bh1, bh2, bh3, ah + (u32)(p * 4096));
        ldsm4(bl0, bl1, bl2, bl3, al + (u32)(p * 4096));
        mma16816(acc[2 * p],     ahi, bh0, bh1);
        mma16816(acc[2 * p + 1], ahi, bh2, bh3);
        mma16816(acc[2 * p],     ahi, bl0, bl1);
        mma16816(acc[2 * p + 1], ahi, bl2, bl3);
        mma16816(acc[2 * p],     alo, bh0, bh1);
        mma16816(acc[2 * p + 1], alo, bh2, bh3);
    }
}

// X @ W_ih^T with streamed global loads of X (distance-1 double buffer)
__device__ __forceinline__ void gemm1(
    float (*acc)[4], float2 (&xb)[2][4],
    const float* pxa, const float* pxb,
    const float* pxa_n, const float* pxb_n,
    u32 base_hi, u32 base_lo, u32 rowpart, int khalf, int r)
{
    #pragma unroll
    for (int kc = 0; kc < 8; kc++) {
        u32 afh[4], afl[4];
        {
            const float2* cur = xb[kc & 1];
            split2(cur[0].x, cur[0].y, afh[0], afl[0]);   // a0: row gr,   k-lo
            split2(cur[2].x, cur[2].y, afh[1], afl[1]);   // a1: row gr+8, k-lo
            split2(cur[1].x, cur[1].y, afh[2], afl[2]);   // a2: row gr,   k-hi
            split2(cur[3].x, cur[3].y, afh[3], afl[3]);   // a3: row gr+8, k-hi
        }
        {   // prefetch chunk kc+1 (chunk 8 -> next step's chunk 0)
            const float* A = (kc + 1 < 8) ? pxa : pxa_n;
            const float* B = (kc + 1 < 8) ? pxb : pxb_n;
            int col = ((kc + 1) & 7) * 16;
            float2* dst = xb[(kc + 1) & 1];
            dst[0] = *(const float2*)(A + col);
            dst[1] = *(const float2*)(A + col + 8);
            dst[2] = *(const float2*)(B + col);
            dst[3] = *(const float2*)(B + col + 8);
        }
        gemm_chunk(acc, afh, afl, base_hi, base_lo, rowpart, khalf, r, kc);
    }
}

__global__ void __launch_bounds__(NTHR, 1) grn_fused(
    const float* __restrict__ X, const float* __restrict__ W_ih,
    const float* __restrict__ W_hh, const float* __restrict__ b_ih,
    const float* __restrict__ b_hh, const float* __restrict__ ln_g,
    const float* __restrict__ ln_b, const float* __restrict__ attn_W,
    const float* __restrict__ dense_W, const float* __restrict__ dense_b,
    float* __restrict__ out)
{
    extern __shared__ char smem[];
    const u32 sb = (u32)__cvta_generic_to_shared(smem);
    const int tid = threadIdx.x;

    // ================= init: build swizzled bf16 hi/lo tiles =================
    // Weights stored [n][k], 256B rows, 16B chunks XOR-swizzled by (n&7).
    #pragma unroll 1
    for (int idx = tid; idx < 16384; idx += NTHR) {
        int m = idx >> 13;
        int i = idx & 8191;
        int n = i >> 6, k = (i & 63) * 2;
        const float* W = m ? W_hh : W_ih;
        float2 wv = *(const float2*)(W + n * 128 + k);
        u32 hi, lo; split2(wv.x, wv.y, hi, lo);
        u32 off = (m ? S_WHH_HI : S_WIH_HI)
                + (u32)(n * 256 + (((k >> 3) ^ (n & 7)) << 4) + (k & 7) * 2);
        *(u32*)(smem + off) = hi;
        *(u32*)(smem + off + 32768u) = lo;
    }
    // E matrix rows: v0 = gamma*attn_W, v1..10 = gamma*dense_W[c], v11..15 = 0
    #pragma unroll 1
    for (int idx = tid; idx < 1024; idx += NTHR) {
        int v = idx >> 6, k = (idx & 63) * 2;
        float g0 = ln_g[k], g1 = ln_g[k + 1];
        float e0 = 0.f, e1 = 0.f;
        if (v == 0)       { e0 = g0 * attn_W[k];                 e1 = g1 * attn_W[k + 1]; }
        else if (v <= 10) { e0 = g0 * dense_W[(v - 1) * 128 + k]; e1 = g1 * dense_W[(v - 1) * 128 + k + 1]; }
        u32 hi, lo; split2(e0, e1, hi, lo);
        u32 off = (u32)(v * 256 + (((k >> 3) ^ (v & 7)) << 4) + (k & 7) * 2);
        *(u32*)(smem + S_E_HI + off) = hi;
        *(u32*)(smem + S_E_LO + off) = lo;
    }
    if (tid < 128) ((float*)(smem + S_BIAS))[tid] = b_ih[tid] + b_hh[tid];
    if (tid < 16) {
        float G = 0.f, B = 0.f;
        if (tid == 0) {
            for (int k = 0; k < 128; k++) { G += ln_g[k] * attn_W[k]; B += ln_b[k] * attn_W[k]; }
        } else if (tid <= 10) {
            const float* dw = dense_W + (tid - 1) * 128;
            for (int k = 0; k < 128; k++) { G += ln_g[k] * dw[k]; B += ln_b[k] * dw[k]; }
        }
        ((float*)(smem + S_GV))[tid] = G;
        ((float*)(smem + S_BV))[tid] = B;
    }
    if (tid < CC) ((float*)(smem + S_DB))[tid] = dense_b[tid];
    __syncthreads();

    // ================= per-warp geometry =================
    const int lane = tid & 31, w = tid >> 5;
    const int gr = lane >> 2, q = lane & 3;
    const int r = lane & 7;
    const int khalf = (lane >> 3) & 1;
    const u32 rowpart = (u32)((((lane >> 4) * 8) + r) * 256);

    const int n0 = blockIdx.x * MB + w * 16 + gr;  // row A
    const int n1 = n0 + 8;                         // row B
    const int r0c = (n0 < NN) ? n0 : (NN - 1);
    const int r1c = (n1 < NN) ? n1 : (NN - 1);
    const float* pxa0 = X + (size_t)r0c * 128 + 2 * q;
    const float* pxb0 = X + (size_t)r1c * 128 + 2 * q;

    // epilogue per-lane constants: owned E-columns {2q, 2q+1, 8+2q, 8+2q+1}
    float Gs[4], Bs[4];
    {
        const float* GV = (const float*)(smem + S_GV);
        const float* BV = (const float*)(smem + S_BV);
        int C0 = 2 * q, C1 = 2 * q + 1, C2 = 8 + 2 * q, C3 = 9 + 2 * q;
        Gs[0] = GV[C0]; Gs[1] = GV[C1]; Gs[2] = GV[C2]; Gs[3] = GV[C3];
        Bs[0] = BV[C0]; Bs[1] = BV[C1]; Bs[2] = BV[C2]; Bs[3] = BV[C3];
    }

    float acc[16][4];
    u32 ah[8][4], al[8][4];
    float2 xb[2][4];

    // preload chunk 0 of X[0]
    xb[0][0] = *(const float2*)(pxa0);
    xb[0][1] = *(const float2*)(pxa0 + 8);
    xb[0][2] = *(const float2*)(pxb0);
    xb[0][3] = *(const float2*)(pxb0 + 8);

    // ================= h0 = X0 @ W_ih^T + bias (no relu) =================
    #pragma unroll
    for (int j = 0; j < 16; j++) {
        float2 b = *(const float2*)((const float*)(smem + S_BIAS) + j * 8 + 2 * q);
        acc[j][0] = b.x; acc[j][1] = b.y; acc[j][2] = b.x; acc[j][3] = b.y;
    }
    gemm1(acc, xb, pxa0, pxb0, pxa0, pxb0,
          sb + S_WIH_HI, sb + S_WIH_LO, rowpart, khalf, r);
    #pragma unroll
    for (int kc = 0; kc < 8; kc++) {
        split2(acc[2 * kc][0],     acc[2 * kc][1],     ah[kc][0], al[kc][0]);
        split2(acc[2 * kc][2],     acc[2 * kc][3],     ah[kc][1], al[kc][1]);
        split2(acc[2 * kc + 1][0], acc[2 * kc + 1][1], ah[kc][2], al[kc][2]);
        split2(acc[2 * kc + 1][2], acc[2 * kc + 1][3], ah[kc][3], al[kc][3]);
    }

    // online softmax state for both rows
    float ma = -1e30f, ssa = 0.f, mb = -1e30f, ssb = 0.f;
    float aca[4] = {0.f, 0.f, 0.f, 0.f}, acb[4] = {0.f, 0.f, 0.f, 0.f};

    // ================= recurrence over t =================
    #pragma unroll 1
    for (int t = 0; t < TT; t++) {
        size_t off  = (size_t)t * NN * 128;
        size_t offn = (size_t)((t < TT - 1) ? t + 1 : t) * NN * 128;

        #pragma unroll
        for (int j = 0; j < 16; j++) {
            float2 b = *(const float2*)((const float*)(smem + S_BIAS) + j * 8 + 2 * q);
            acc[j][0] = b.x; acc[j][1] = b.y; acc[j][2] = b.x; acc[j][3] = b.y;
        }
        // pre = X_t @ W_ih^T + bias   (streamed X)
        gemm1(acc, xb, pxa0 + off, pxb0 + off, pxa0 + offn, pxb0 + offn,
              sb + S_WIH_HI, sb + S_WIH_LO, rowpart, khalf, r);
        // pre += h @ W_hh^T
        #pragma unroll
        for (int kc = 0; kc < 8; kc++)
            gemm_chunk(acc, ah[kc], al[kc], sb + S_WHH_HI, sb + S_WHH_LO,
                       rowpart, khalf, r, kc);

        // relu + row stats from fragments
        float s1a = 0.f, s2a = 0.f, s1b = 0.f, s2b = 0.f;
        #pragma unroll
        for (int j = 0; j < 16; j++) {
            acc[j][0] = fmaxf(acc[j][0], 0.f);
            acc[j][1] = fmaxf(acc[j][1], 0.f);
            acc[j][2] = fmaxf(acc[j][2], 0.f);
            acc[j][3] = fmaxf(acc[j][3], 0.f);
            s1a += acc[j][0] + acc[j][1];
            s2a += acc[j][0] * acc[j][0] + acc[j][1] * acc[j][1];
            s1b += acc[j][2] + acc[j][3];
            s2b += acc[j][2] * acc[j][2] + acc[j][3] * acc[j][3];
        }
        // D-fragments ARE next A-fragments: convert in place
        #pragma unroll
        for (int kc = 0; kc < 8; kc++) {
            split2(acc[2 * kc][0],     acc[2 * kc][1],     ah[kc][0], al[kc][0]);
            split2(acc[2 * kc][2],     acc[2 * kc][3],     ah[kc][1], al[kc][1]);
            split2(acc[2 * kc + 1][0], acc[2 * kc + 1][1], ah[kc][2], al[kc][2]);
            split2(acc[2 * kc + 1][2], acc[2 * kc + 1][3], ah[kc][3], al[kc][3]);
        }
        s1a += __shfl_xor_sync(~0u, s1a, 1); s1a += __shfl_xor_sync(~0u, s1a, 2);
        s2a += __shfl_xor_sync(~0u, s2a, 1); s2a += __shfl_xor_sync(~0u, s2a, 2);
        s1b += __shfl_xor_sync(~0u, s1b, 1); s1b += __shfl_xor_sync(~0u, s1b, 2);
        s2b += __shfl_xor_sync(~0u, s2b, 1); s2b += __shfl_xor_sync(~0u, s2b, 2);
        float mua = s1a * (1.f / 128.f);
        float mub = s1b * (1.f / 128.f);
        float rsa = rsqrtf(s2a * (1.f / 128.f) - mua * mua + LN_EPS);
        float rsb = rsqrtf(s2b * (1.f / 128.f) - mub * mub + LN_EPS);

        // S = h @ E  (16 cols: attn + 10 dense + pad)
        float ea[2][4] = {{0.f, 0.f, 0.f, 0.f}, {0.f, 0.f, 0.f, 0.f}};
        #pragma unroll
        for (int kc = 0; kc < 8; kc++) {
            u32 sw = (u32)(((2 * kc + khalf) ^ r) << 4);
            u32 eh0, eh1, eh2, eh3, el0, el1, el2, el3;
            ldsm4(eh0, eh1, eh2, eh3, sb + S_E_HI + rowpart + sw);
            ldsm4(el0, el1, el2, el3, sb + S_E_LO + rowpart + sw);
            mma16816(ea[0], ah[kc], eh0, eh1);
            mma16816(ea[1], ah[kc], eh2, eh3);
            mma16816(ea[0], ah[kc], el0, el1);
            mma16816(ea[1], ah[kc], el2, el3);
            mma16816(ea[0], al[kc], eh0, eh1);
            mma16816(ea[1], al[kc], eh2, eh3);
        }

        // y.v = rstd*(S - mu*G) + B per owned col; col0 (attn) broadcast as logit
        float dva[4], dvb[4];
        dva[0] = rsa * (ea[0][0] - mua * Gs[0]) + Bs[0];
        dva[1] = rsa * (ea[0][1] - mua * Gs[1]) + Bs[1];
        dva[2] = rsa * (ea[1][0] - mua * Gs[2]) + Bs[2];
        dva[3] = rsa * (ea[1][1] - mua * Gs[3]) + Bs[3];
        dvb[0] = rsb * (ea[0][2] - mub * Gs[0]) + Bs[0];
        dvb[1] = rsb * (ea[0][3] - mub * Gs[1]) + Bs[1];
        dvb[2] = rsb * (ea[1][2] - mub * Gs[2]) + Bs[2];
        dvb[3] = rsb * (ea[1][3] - mub * Gs[3]) + Bs[3];
        float la = __shfl_sync(~0u, dva[0], lane & ~3);
        float lb = __shfl_sync(~0u, dvb[0], lane & ~3);

        float nma = fmaxf(ma, la);
        float eoa = __expf(ma - nma), ena = __expf(la - nma);
        ssa = ssa * eoa + ena; ma = nma;
        float nmb = fmaxf(mb, lb);
        float eob = __expf(mb - nmb), enb = __expf(lb - nmb);
        ssb = ssb * eob + enb; mb = nmb;
        #pragma unroll
        for (int s = 0; s < 4; s++) {
            aca[s] = aca[s] * eoa + ena * dva[s];
            acb[s] = acb[s] * eob + enb * dvb[s];
        }
    }

    // ================= output =================
    const float* db = (const float*)(smem + S_DB);
    float inva = 1.f / ssa, invb = 1.f / ssb;
    #pragma unroll
    for (int s = 0; s < 4; s++) {
        int e = (s < 2) ? (2 * q + s) : (8 + 2 * q + (s - 2));
        if (e >= 1 && e <= 10) {
            int c = e - 1;
            if (n0 < NN) out[n0 * CC + c] = aca[s] * inva + db[c];
            if (n1 < NN) out[n1 * CC + c] = acb[s] * invb + db[c];
        }
    }
}

// ---------------------------------------------------------------------------
extern "C" void kernel_launch(void* const* d_in, const int* in_sizes, int n_in,
                              void* d_out, int out_size) {
    (void)in_sizes; (void)n_in; (void)out_size;
    const float* X       = (const float*)d_in[0];
    const float* W_ih    = (const float*)d_in[1];
    const float* W_hh    = (const float*)d_in[2];
    const float* b_ih    = (const float*)d_in[3];
    const float* b_hh    = (const float*)d_in[4];
    const float* ln_g    = (const float*)d_in[5];
    const float* ln_b    = (const float*)d_in[6];
    const float* attn_W  = (const float*)d_in[7];
    // d_in[8] = attn_b: cancels in softmax over time.
    const float* dense_W = (const float*)d_in[9];
    const float* dense_b = (const float*)d_in[10];
    float* out = (float*)d_out;

    cudaFuncSetAttribute(grn_fused, cudaFuncAttributeMaxDynamicSharedMemorySize, S_TOTAL);
    grn_fused<<<NCTA, NTHR, S_TOTAL>>>(X, W_ih, W_hh, b_ih, b_hh, ln_g, ln_b,
                                       attn_W, dense_W, dense_b, out);
}